// round 4
// baseline (speedup 1.0000x reference)
#include <cuda_runtime.h>
#include <cuda_bf16.h>

// MetaPolicyTransformer: N independent sequences, S=5, D=4, H=2 (hd=2), FF=16, L=3.
// 2 sequences per thread packed into f32x2. Activations x live in SMEM (SoA,
// thread-private, conflict-free); registers hold only the residual accumulator,
// one head's K/V, and row temps -> no spills (R2/R3 hit the 255-reg ceiling).

#define D_ 4
#define S_ 5
#define FF_ 16
#define L_ 3
#define BLK 128

typedef unsigned long long u64;

__device__ __forceinline__ u64 pk2(float lo, float hi) {
    u64 r; asm("mov.b64 %0, {%1, %2};" : "=l"(r) : "f"(lo), "f"(hi)); return r;
}
__device__ __forceinline__ void upk2(u64 v, float& lo, float& hi) {
    asm("mov.b64 {%0, %1}, %2;" : "=f"(lo), "=f"(hi) : "l"(v));
}
__device__ __forceinline__ u64 fma2(u64 a, u64 b, u64 c) {
    u64 r; asm("fma.rn.f32x2 %0, %1, %2, %3;" : "=l"(r) : "l"(a), "l"(b), "l"(c)); return r;
}
__device__ __forceinline__ u64 add2(u64 a, u64 b) {
    u64 r; asm("add.rn.f32x2 %0, %1, %2;" : "=l"(r) : "l"(a), "l"(b)); return r;
}
__device__ __forceinline__ u64 mul2(u64 a, u64 b) {
    u64 r; asm("mul.rn.f32x2 %0, %1, %2;" : "=l"(r) : "l"(a), "l"(b)); return r;
}
__device__ __forceinline__ float ex2a(float x) {
    float r; asm("ex2.approx.f32 %0, %1;" : "=f"(r) : "f"(x)); return r;
}
__device__ __forceinline__ float rcpa(float x) {
    float r; asm("rcp.approx.f32 %0, %1;" : "=f"(r) : "f"(x)); return r;
}
__device__ __forceinline__ u64 relu2(u64 v) {
    float a, b; upk2(v, a, b);
    return pk2(fmaxf(a, 0.0f), fmaxf(b, 0.0f));
}

__global__ __launch_bounds__(BLK, 3) void mpt_kernel(
    const float* __restrict__ xin,   // (N, 4, 4)
    const float* __restrict__ cls,   // (4,)
    const float* __restrict__ Wqkv,  // (3, 12, 4)
    const float* __restrict__ bqkv,  // (3, 12)
    const float* __restrict__ Wo,    // (3, 4, 4)
    const float* __restrict__ bo,    // (3, 4)
    const float* __restrict__ W1,    // (3, 16, 4)
    const float* __restrict__ b1,    // (3, 16)
    const float* __restrict__ W2,    // (3, 4, 16)
    const float* __restrict__ b2,    // (3, 4)
    float* __restrict__ out_fg,      // (N, 4)
    float* __restrict__ out_sub,     // (N, 16)
    int N)
{
    // Weights packed {w,w}; q-rows of Wqkv/bqkv pre-multiplied by scale*log2(e)
    __shared__ u64 sWqkv[L_ * 48];
    __shared__ u64 sbqkv[L_ * 12];
    __shared__ u64 sWo[L_ * 16];
    __shared__ u64 sbo[L_ * 4];
    __shared__ u64 sW1[L_ * 64];
    __shared__ u64 sb1[L_ * 16];
    __shared__ u64 sW2[L_ * 64];
    __shared__ u64 sb2[L_ * 4];
    __shared__ float scls[4];
    // activations, SoA: sx[s*4+d][tid] -> conflict-free 64-bit LDS/STS
    __shared__ u64 sx[S_ * D_][BLK];

    const float SCL = 0.70710678118654752f * 1.4426950408889634f; // 1/sqrt(2)*log2e

    const int t = threadIdx.x;
    for (int i = t; i < L_ * 48; i += BLK) {
        float w = Wqkv[i];
        if (((i >> 2) % 12) < 4) w *= SCL;       // q rows pre-scaled
        sWqkv[i] = pk2(w, w);
    }
    for (int i = t; i < L_ * 12; i += BLK) {
        float w = bqkv[i];
        if ((i % 12) < 4) w *= SCL;
        sbqkv[i] = pk2(w, w);
    }
    for (int i = t; i < L_ * 16; i += BLK) { float w = Wo[i]; sWo[i] = pk2(w, w); }
    for (int i = t; i < L_ * 4;  i += BLK) { float w = bo[i]; sbo[i] = pk2(w, w); }
    for (int i = t; i < L_ * 64; i += BLK) { float w = W1[i]; sW1[i] = pk2(w, w); }
    for (int i = t; i < L_ * 16; i += BLK) { float w = b1[i]; sb1[i] = pk2(w, w); }
    for (int i = t; i < L_ * 64; i += BLK) { float w = W2[i]; sW2[i] = pk2(w, w); }
    for (int i = t; i < L_ * 4;  i += BLK) { float w = b2[i]; sb2[i] = pk2(w, w); }
    if (t < 4) scls[t] = cls[t];
    __syncthreads();

    const int n0 = blockIdx.x * (2 * BLK) + t;
    const int n1 = n0 + BLK;
    if (n0 >= N) return;
    const bool okB = (n1 < N);
    const int nB = okB ? n1 : n0;

    // PE: pe[s] = [sin(s), cos(s), sin(.01 s), cos(.01 s)]
    const float pe[S_][D_] = {
        { 0.0f,                  1.0f,                  0.0f,                   1.0f                 },
        { 0.84147098480789651f,  0.54030230586813977f,  0.0099998333341666645f, 0.99995000041666528f },
        { 0.90929742682568170f, -0.41614683654714241f,  0.019998666693333084f,  0.99980000666657776f },
        { 0.14112000805986722f, -0.98999249660044542f,  0.029995500337493652f,  0.99955003374899023f },
        { -0.75680249530792820f,-0.65364362086361194f,  0.039989334186634161f,  0.99920010665856564f }
    };

    // init x in smem
    #pragma unroll
    for (int d = 0; d < D_; d++) {
        float c = scls[d] + pe[0][d];
        sx[d][t] = pk2(c, c);
    }
    {
        const float4* xa = reinterpret_cast<const float4*>(xin + (size_t)n0 * 16);
        const float4* xb = reinterpret_cast<const float4*>(xin + (size_t)nB * 16);
        #pragma unroll
        for (int s = 1; s < S_; s++) {
            float4 ra = xa[s - 1];
            float4 rb = xb[s - 1];
            sx[s * 4 + 0][t] = pk2(ra.x + pe[s][0], rb.x + pe[s][0]);
            sx[s * 4 + 1][t] = pk2(ra.y + pe[s][1], rb.y + pe[s][1]);
            sx[s * 4 + 2][t] = pk2(ra.z + pe[s][2], rb.z + pe[s][2]);
            sx[s * 4 + 3][t] = pk2(ra.w + pe[s][3], rb.w + pe[s][3]);
        }
    }

    u64 nx[S_][D_];   // residual accumulator, lives across the layer

    #pragma unroll 1
    for (int l = 0; l < L_; l++) {
        const u64* wq  = sWqkv + l * 48;
        const u64* bq  = sbqkv + l * 12;
        const u64* wo  = sWo   + l * 16;
        const u64* bov = sbo   + l * 4;
        const u64* w1  = sW1   + l * 64;
        const u64* b1v = sb1   + l * 16;
        const u64* w2  = sW2   + l * 64;
        const u64* b2v = sb2   + l * 4;

        // nx = x + bo  (out-proj bias folded in; heads accumulate below)
        #pragma unroll
        for (int s = 0; s < S_; s++)
            #pragma unroll
            for (int d = 0; d < D_; d++)
                nx[s][d] = add2(sx[s * 4 + d][t], bov[d]);

        #pragma unroll 1
        for (int h = 0; h < 2; h++) {
            // K, V for this head only (20 u64)
            u64 kh[S_][2], vh[S_][2];
            #pragma unroll
            for (int s = 0; s < S_; s++) {
                u64 xc[D_];
                #pragma unroll
                for (int c = 0; c < D_; c++) xc[c] = sx[s * 4 + c][t];
                #pragma unroll
                for (int e = 0; e < 2; e++) {
                    const int o = 2 * h + e;
                    u64 ak = bq[4 + o], av = bq[8 + o];
                    #pragma unroll
                    for (int c = 0; c < D_; c++) {
                        ak = fma2(xc[c], wq[(4 + o) * 4 + c], ak);
                        av = fma2(xc[c], wq[(8 + o) * 4 + c], av);
                    }
                    kh[s][e] = ak;
                    vh[s][e] = av;
                }
            }
            #pragma unroll
            for (int i = 0; i < S_; i++) {
                // q_i on the fly (weights already carry scale*log2e)
                u64 xc[D_];
                #pragma unroll
                for (int c = 0; c < D_; c++) xc[c] = sx[i * 4 + c][t];
                u64 q0 = bq[2 * h], q1 = bq[2 * h + 1];
                #pragma unroll
                for (int c = 0; c < D_; c++) {
                    q0 = fma2(xc[c], wq[(2 * h) * 4 + c], q0);
                    q1 = fma2(xc[c], wq[(2 * h + 1) * 4 + c], q1);
                }
                u64 e[S_], sum = 0ull;
                #pragma unroll
                for (int j = 0; j < S_; j++) {
                    u64 sc = fma2(q1, kh[j][1], mul2(q0, kh[j][0]));
                    float a, b; upk2(sc, a, b);
                    e[j] = pk2(ex2a(a), ex2a(b));
                    sum = add2(sum, e[j]);
                }
                float sa, sb; upk2(sum, sa, sb);
                u64 inv = pk2(rcpa(sa), rcpa(sb));
                u64 o0 = 0ull, o1 = 0ull;
                #pragma unroll
                for (int j = 0; j < S_; j++) {
                    o0 = fma2(e[j], vh[j][0], o0);
                    o1 = fma2(e[j], vh[j][1], o1);
                }
                o0 = mul2(o0, inv);
                o1 = mul2(o1, inv);
                // fused out-projection (columns 2h, 2h+1 of Wo)
                #pragma unroll
                for (int d = 0; d < D_; d++) {
                    nx[i][d] = fma2(o0, wo[d * 4 + 2 * h],     nx[i][d]);
                    nx[i][d] = fma2(o1, wo[d * 4 + 2 * h + 1], nx[i][d]);
                }
            }
        }

        // FF + residual; write next-layer x back to smem
        #pragma unroll
        for (int s = 0; s < S_; s++) {
            u64 h1[FF_];
            #pragma unroll
            for (int f = 0; f < FF_; f++) {
                u64 a = b1v[f];
                #pragma unroll
                for (int c = 0; c < D_; c++)
                    a = fma2(nx[s][c], w1[f * 4 + c], a);
                h1[f] = relu2(a);
            }
            #pragma unroll
            for (int d = 0; d < D_; d++) {
                u64 a = b2v[d];
                #pragma unroll
                for (int f = 0; f < FF_; f++)
                    a = fma2(h1[f], w2[d * 16 + f], a);
                nx[s][d] = add2(nx[s][d], a);
            }
            if (l != L_ - 1) {
                #pragma unroll
                for (int d = 0; d < D_; d++)
                    sx[s * 4 + d][t] = nx[s][d];
            }
        }
    }

    // outputs straight from nx (last layer's result)
    {
        float a0, b0, a1, b1f, a2, b2f, a3, b3;
        upk2(nx[0][0], a0, b0); upk2(nx[0][1], a1, b1f);
        upk2(nx[0][2], a2, b2f); upk2(nx[0][3], a3, b3);
        reinterpret_cast<float4*>(out_fg + (size_t)n0 * 4)[0] = make_float4(a0, a1, a2, a3);
        if (okB)
            reinterpret_cast<float4*>(out_fg + (size_t)n1 * 4)[0] = make_float4(b0, b1f, b2f, b3);
    }
    float4* subA = reinterpret_cast<float4*>(out_sub + (size_t)n0 * 16);
    float4* subB = reinterpret_cast<float4*>(out_sub + (size_t)n1 * 16);
    #pragma unroll
    for (int s = 1; s < S_; s++) {
        float a0, b0, a1, b1f, a2, b2f, a3, b3;
        upk2(nx[s][0], a0, b0); upk2(nx[s][1], a1, b1f);
        upk2(nx[s][2], a2, b2f); upk2(nx[s][3], a3, b3);
        subA[s - 1] = make_float4(a0, a1, a2, a3);
        if (okB) subB[s - 1] = make_float4(b0, b1f, b2f, b3);
    }
}

extern "C" void kernel_launch(void* const* d_in, const int* in_sizes, int n_in,
                              void* d_out, int out_size) {
    const float* xin  = (const float*)d_in[0];
    const float* cls  = (const float*)d_in[1];
    const float* Wqkv = (const float*)d_in[2];
    const float* bqkv = (const float*)d_in[3];
    const float* Wo   = (const float*)d_in[4];
    const float* bo   = (const float*)d_in[5];
    const float* W1   = (const float*)d_in[6];
    const float* b1   = (const float*)d_in[7];
    const float* W2   = (const float*)d_in[8];
    const float* b2   = (const float*)d_in[9];

    const int N = in_sizes[0] / 16;
    float* out_fg  = (float*)d_out;
    float* out_sub = (float*)d_out + (size_t)N * 4;

    const int grid = (N + 2 * BLK - 1) / (2 * BLK);
    mpt_kernel<<<grid, BLK>>>(xin, cls, Wqkv, bqkv, Wo, bo, W1, b1, W2, b2,
                              out_fg, out_sub, N);
}

// round 5
// speedup vs baseline: 3.4134x; 3.4134x over previous
#include <cuda_runtime.h>
#include <cuda_bf16.h>

// MetaPolicyTransformer: N independent sequences, S=5, D=4, H=2 (hd=2), FF=16, L=3.
// ONE sequence per thread (R1 structure, no spills), f32x2 packed across the
// MODEL dimension: head dim (=2) is exactly one f32x2 pair, so q/k/v/out-proj/FF
// all run on packed math. Broadcast dups go to the ALU pipe (idle in R1).

#define D_ 4
#define S_ 5
#define FF_ 16
#define L_ 3
#define BLK 128

typedef unsigned long long u64;

__device__ __forceinline__ u64 pk2(float lo, float hi) {
    u64 r; asm("mov.b64 %0, {%1, %2};" : "=l"(r) : "f"(lo), "f"(hi)); return r;
}
__device__ __forceinline__ void upk2(u64 v, float& lo, float& hi) {
    asm("mov.b64 {%0, %1}, %2;" : "=f"(lo), "=f"(hi) : "l"(v));
}
__device__ __forceinline__ u64 fma2(u64 a, u64 b, u64 c) {
    u64 r; asm("fma.rn.f32x2 %0, %1, %2, %3;" : "=l"(r) : "l"(a), "l"(b), "l"(c)); return r;
}
__device__ __forceinline__ u64 add2(u64 a, u64 b) {
    u64 r; asm("add.rn.f32x2 %0, %1, %2;" : "=l"(r) : "l"(a), "l"(b)); return r;
}
__device__ __forceinline__ u64 mul2(u64 a, u64 b) {
    u64 r; asm("mul.rn.f32x2 %0, %1, %2;" : "=l"(r) : "l"(a), "l"(b)); return r;
}
__device__ __forceinline__ float ex2a(float x) {
    float r; asm("ex2.approx.f32 %0, %1;" : "=f"(r) : "f"(x)); return r;
}
__device__ __forceinline__ float rcpa(float x) {
    float r; asm("rcp.approx.f32 %0, %1;" : "=f"(r) : "f"(x)); return r;
}
__device__ __forceinline__ u64 relu2(u64 v) {
    float a, b; upk2(v, a, b);
    return pk2(fmaxf(a, 0.0f), fmaxf(b, 0.0f));
}

__global__ __launch_bounds__(BLK) void mpt_kernel(
    const float* __restrict__ xin,   // (N, 4, 4)
    const float* __restrict__ cls,   // (4,)
    const float* __restrict__ Wqkv,  // (3, 12, 4)
    const float* __restrict__ bqkv,  // (3, 12)
    const float* __restrict__ Wo,    // (3, 4, 4)
    const float* __restrict__ bo,    // (3, 4)
    const float* __restrict__ W1,    // (3, 16, 4)
    const float* __restrict__ b1,    // (3, 16)
    const float* __restrict__ W2,    // (3, 4, 16)
    const float* __restrict__ b2,    // (3, 4)
    float* __restrict__ out_fg,      // (N, 4)
    float* __restrict__ out_sub,     // (N, 16)
    int N)
{
    // Weights packed across OUTPUT pairs:
    // sQKV[l][p][c] = {Wqkv[2p][c], Wqkv[2p+1][c]}, q rows (p<2) pre-scaled by 1/sqrt(2)*log2e
    __shared__ u64 sQKV[L_ * 24];
    __shared__ u64 sBQ[L_ * 6];
    __shared__ u64 sWO[L_ * 8];    // [dp][c] = {Wo[2dp][c], Wo[2dp+1][c]}
    __shared__ u64 sBO[L_ * 2];    // {bo[2dp], bo[2dp+1]}
    __shared__ u64 sW1[L_ * 32];   // [fp][c] = {W1[2fp][c], W1[2fp+1][c]}
    __shared__ u64 sB1[L_ * 8];
    __shared__ u64 sW2[L_ * 32];   // [d][fp] = {W2[d][2fp], W2[d][2fp+1]}
    __shared__ float sB2[L_ * 4];
    __shared__ float scls[4];

    const float SCL = 0.70710678118654752f * 1.4426950408889634f; // 1/sqrt2 * log2e

    const int t = threadIdx.x;
    for (int i = t; i < L_ * 24; i += BLK) {
        int l = i / 24, rem = i % 24, p = rem / 4, c = rem % 4;
        float w0 = Wqkv[l * 48 + (2 * p)     * 4 + c];
        float w1 = Wqkv[l * 48 + (2 * p + 1) * 4 + c];
        if (p < 2) { w0 *= SCL; w1 *= SCL; }
        sQKV[i] = pk2(w0, w1);
    }
    for (int i = t; i < L_ * 6; i += BLK) {
        int l = i / 6, p = i % 6;
        float b0 = bqkv[l * 12 + 2 * p];
        float b1v = bqkv[l * 12 + 2 * p + 1];
        if (p < 2) { b0 *= SCL; b1v *= SCL; }
        sBQ[i] = pk2(b0, b1v);
    }
    for (int i = t; i < L_ * 8; i += BLK) {
        int l = i / 8, rem = i % 8, dp = rem / 4, c = rem % 4;
        sWO[i] = pk2(Wo[l * 16 + (2 * dp) * 4 + c], Wo[l * 16 + (2 * dp + 1) * 4 + c]);
    }
    for (int i = t; i < L_ * 2; i += BLK) {
        int l = i / 2, dp = i % 2;
        sBO[i] = pk2(bo[l * 4 + 2 * dp], bo[l * 4 + 2 * dp + 1]);
    }
    for (int i = t; i < L_ * 32; i += BLK) {
        int l = i / 32, rem = i % 32, fp = rem / 4, c = rem % 4;
        sW1[i] = pk2(W1[l * 64 + (2 * fp) * 4 + c], W1[l * 64 + (2 * fp + 1) * 4 + c]);
    }
    for (int i = t; i < L_ * 8; i += BLK) {
        int l = i / 8, fp = i % 8;
        sB1[i] = pk2(b1[l * 16 + 2 * fp], b1[l * 16 + 2 * fp + 1]);
    }
    for (int i = t; i < L_ * 32; i += BLK) {
        int l = i / 32, rem = i % 32, d = rem / 8, fp = rem % 8;
        sW2[i] = pk2(W2[l * 64 + d * 16 + 2 * fp], W2[l * 64 + d * 16 + 2 * fp + 1]);
    }
    for (int i = t; i < L_ * 4; i += BLK) sB2[i] = b2[i];
    if (t < 4) scls[t] = cls[t];
    __syncthreads();

    const int n = blockIdx.x * BLK + t;
    if (n >= N) return;

    // PE: pe[s] = [sin(s), cos(s), sin(.01 s), cos(.01 s)]
    const float pe[S_][D_] = {
        { 0.0f,                  1.0f,                  0.0f,                   1.0f                 },
        { 0.84147098480789651f,  0.54030230586813977f,  0.0099998333341666645f, 0.99995000041666528f },
        { 0.90929742682568170f, -0.41614683654714241f,  0.019998666693333084f,  0.99980000666657776f },
        { 0.14112000805986722f, -0.98999249660044542f,  0.029995500337493652f,  0.99955003374899023f },
        { -0.75680249530792820f,-0.65364362086361194f,  0.039989334186634161f,  0.99920010665856564f }
    };

    float x[S_][D_];
    #pragma unroll
    for (int d = 0; d < D_; d++) x[0][d] = scls[d] + pe[0][d];
    const float4* xp = reinterpret_cast<const float4*>(xin + (size_t)n * 16);
    #pragma unroll
    for (int s = 1; s < S_; s++) {
        float4 r = xp[s - 1];
        x[s][0] = r.x + pe[s][0];
        x[s][1] = r.y + pe[s][1];
        x[s][2] = r.z + pe[s][2];
        x[s][3] = r.w + pe[s][3];
    }

    #pragma unroll 1
    for (int l = 0; l < L_; l++) {
        const u64* wq   = sQKV + l * 24;
        const u64* bqp  = sBQ  + l * 6;
        const u64* wop  = sWO  + l * 8;
        const u64* bop  = sBO  + l * 2;
        const u64* w1p  = sW1  + l * 32;
        const u64* b1p  = sB1  + l * 8;
        const u64* w2p  = sW2  + l * 32;
        const float* b2s = sB2 + l * 4;

        // residual accumulator (packed by output pairs), out-proj bias folded in
        u64 nxp[S_][2];
        #pragma unroll
        for (int s = 0; s < S_; s++) {
            nxp[s][0] = add2(pk2(x[s][0], x[s][1]), bop[0]);
            nxp[s][1] = add2(pk2(x[s][2], x[s][3]), bop[1]);
        }

        // QKV: packed output pairs; pair h of q/k/v is exactly head h's 2 dims
        u64 qp[S_][2], kp[S_][2], vp[S_][2];
        #pragma unroll
        for (int s = 0; s < S_; s++) {
            u64 xd[D_];
            #pragma unroll
            for (int c = 0; c < D_; c++) xd[c] = pk2(x[s][c], x[s][c]);
            #pragma unroll
            for (int p = 0; p < 6; p++) {
                u64 a = bqp[p];
                #pragma unroll
                for (int c = 0; c < D_; c++)
                    a = fma2(xd[c], wq[p * 4 + c], a);
                if (p < 2)      qp[s][p]     = a;
                else if (p < 4) kp[s][p - 2] = a;
                else            vp[s][p - 4] = a;
            }
        }

        // attention per head; out-proj fused into nxp
        #pragma unroll
        for (int h = 0; h < 2; h++) {
            #pragma unroll
            for (int i = 0; i < S_; i++) {
                float e[S_];
                float sum = 0.0f;
                #pragma unroll
                for (int j = 0; j < S_; j++) {
                    u64 m = mul2(qp[i][h], kp[j][h]);   // {q0k0, q1k1}
                    float a, b; upk2(m, a, b);
                    e[j] = ex2a(a + b);                  // exp2 of scaled score
                    sum += e[j];
                }
                float inv = rcpa(sum);
                u64 o = 0ull;
                #pragma unroll
                for (int j = 0; j < S_; j++)
                    o = fma2(pk2(e[j], e[j]), vp[j][h], o);
                float a0, a1; upk2(o, a0, a1);
                a0 *= inv; a1 *= inv;
                u64 d0 = pk2(a0, a0), d1 = pk2(a1, a1);
                #pragma unroll
                for (int dp = 0; dp < 2; dp++) {
                    nxp[i][dp] = fma2(d0, wop[dp * 4 + 2 * h],     nxp[i][dp]);
                    nxp[i][dp] = fma2(d1, wop[dp * 4 + 2 * h + 1], nxp[i][dp]);
                }
            }
        }

        // unpack residual result back to scalar x
        #pragma unroll
        for (int s = 0; s < S_; s++) {
            upk2(nxp[s][0], x[s][0], x[s][1]);
            upk2(nxp[s][1], x[s][2], x[s][3]);
        }

        // FF + residual (packed over FF pairs)
        #pragma unroll
        for (int s = 0; s < S_; s++) {
            u64 xd[D_];
            #pragma unroll
            for (int c = 0; c < D_; c++) xd[c] = pk2(x[s][c], x[s][c]);
            u64 h1p[8];
            #pragma unroll
            for (int fp = 0; fp < 8; fp++) {
                u64 a = b1p[fp];
                #pragma unroll
                for (int c = 0; c < D_; c++)
                    a = fma2(xd[c], w1p[fp * 4 + c], a);
                h1p[fp] = relu2(a);
            }
            #pragma unroll
            for (int d = 0; d < D_; d++) {
                u64 a = 0ull;
                #pragma unroll
                for (int fp = 0; fp < 8; fp++)
                    a = fma2(h1p[fp], w2p[d * 8 + fp], a);
                float pa, pb; upk2(a, pa, pb);
                x[s][d] = x[s][d] + b2s[d] + (pa + pb);
            }
        }
    }

    // outputs
    reinterpret_cast<float4*>(out_fg + (size_t)n * 4)[0] =
        make_float4(x[0][0], x[0][1], x[0][2], x[0][3]);
    float4* sub = reinterpret_cast<float4*>(out_sub + (size_t)n * 16);
    #pragma unroll
    for (int s = 1; s < S_; s++)
        sub[s - 1] = make_float4(x[s][0], x[s][1], x[s][2], x[s][3]);
}

extern "C" void kernel_launch(void* const* d_in, const int* in_sizes, int n_in,
                              void* d_out, int out_size) {
    const float* xin  = (const float*)d_in[0];
    const float* cls  = (const float*)d_in[1];
    const float* Wqkv = (const float*)d_in[2];
    const float* bqkv = (const float*)d_in[3];
    const float* Wo   = (const float*)d_in[4];
    const float* bo   = (const float*)d_in[5];
    const float* W1   = (const float*)d_in[6];
    const float* b1   = (const float*)d_in[7];
    const float* W2   = (const float*)d_in[8];
    const float* b2   = (const float*)d_in[9];

    const int N = in_sizes[0] / 16;
    float* out_fg  = (float*)d_out;
    float* out_sub = (float*)d_out + (size_t)N * 4;

    const int grid = (N + BLK - 1) / BLK;
    mpt_kernel<<<grid, BLK>>>(xin, cls, Wqkv, bqkv, Wo, bo, W1, b1, W2, b2,
                              out_fg, out_sub, N);
}